// round 4
// baseline (speedup 1.0000x reference)
#include <cuda_runtime.h>
#include <math.h>

#define B_    4096
#define S_    128
#define D_    128
#define H_    4
#define FF_   256
#define K_    4
#define MROWS (B_ * S_)   // 524288

// ---------------- global scratch (no allocations allowed) ----------------
__device__ float g_h[(size_t)MROWS * 128];     // activations [B*S,128]
__device__ float g_qkv[(size_t)MROWS * 384];   // qkv / ffn-hidden / o-proj out
__device__ float g_attn[(size_t)MROWS * 128];  // attention out / ffn2 out
__device__ float g_comb[(size_t)B_ * 256];     // [time_emb | cond_emb]
__device__ float g_mw[(size_t)B_ * 4];         // mixture weights
__device__ float g_base[(size_t)B_ * 512];     // folded student hidden base
__device__ float g_sw1p[256 * 512];            // packed s_w1[:,2:,:] -> [256,512]

__device__ __forceinline__ float siluf(float x) { return x / (1.f + __expf(-x)); }
__device__ __forceinline__ float tanh_fast(float x) { return 1.f - 2.f / (__expf(2.f * x) + 1.f); }

// ---------------- generic tiled SGEMM: C[M,N] = A[M,K] @ B[K,N] + bias ----------------
// BM=BN=64, BK=16, 64 threads, 8x8 micro-tile per thread. M%64==0, N%64==0, K%16==0.
template <int RELU>
__global__ void __launch_bounds__(64) gemm64(const float* __restrict__ A,
                                             const float* __restrict__ Bm,
                                             const float* __restrict__ bias,
                                             float* __restrict__ C,
                                             int M, int N, int K) {
    __shared__ float As[16][64];   // transposed: As[k][m]
    __shared__ float Bs[16][64];
    const int tid = threadIdx.x;
    const int bm = blockIdx.y * 64;
    const int bn = blockIdx.x * 64;
    const int tx = tid & 7;
    const int ty = tid >> 3;

    float acc[8][8];
#pragma unroll
    for (int i = 0; i < 8; i++)
#pragma unroll
        for (int j = 0; j < 8; j++) acc[i][j] = 0.f;

    const float* Arow = A + (size_t)(bm + tid) * K;
    const int brow = tid & 15;
    const int bcol = (tid >> 4) * 16;

    for (int kk = 0; kk < K; kk += 16) {
        // load A tile (transposed into smem)
#pragma unroll
        for (int c = 0; c < 4; c++) {
            float4 v = *(const float4*)(Arow + kk + c * 4);
            As[c * 4 + 0][tid] = v.x;
            As[c * 4 + 1][tid] = v.y;
            As[c * 4 + 2][tid] = v.z;
            As[c * 4 + 3][tid] = v.w;
        }
        // load B tile
#pragma unroll
        for (int c = 0; c < 4; c++) {
            float4 v = *(const float4*)(Bm + (size_t)(kk + brow) * N + bn + bcol + c * 4);
            *(float4*)&Bs[brow][bcol + c * 4] = v;
        }
        __syncthreads();
#pragma unroll
        for (int k = 0; k < 16; k++) {
            float a[8], b[8];
            *(float4*)&a[0] = *(const float4*)&As[k][ty * 8];
            *(float4*)&a[4] = *(const float4*)&As[k][ty * 8 + 4];
            *(float4*)&b[0] = *(const float4*)&Bs[k][tx * 8];
            *(float4*)&b[4] = *(const float4*)&Bs[k][tx * 8 + 4];
#pragma unroll
            for (int i = 0; i < 8; i++)
#pragma unroll
                for (int j = 0; j < 8; j++) acc[i][j] = fmaf(a[i], b[j], acc[i][j]);
        }
        __syncthreads();
    }

    float bv[8];
#pragma unroll
    for (int j = 0; j < 8; j++) bv[j] = bias[bn + tx * 8 + j];
#pragma unroll
    for (int i = 0; i < 8; i++) {
        float* crow = C + (size_t)(bm + ty * 8 + i) * N + bn + tx * 8;
        float4 r0, r1;
        float v0 = acc[i][0] + bv[0], v1 = acc[i][1] + bv[1];
        float v2 = acc[i][2] + bv[2], v3 = acc[i][3] + bv[3];
        float v4 = acc[i][4] + bv[4], v5 = acc[i][5] + bv[5];
        float v6 = acc[i][6] + bv[6], v7 = acc[i][7] + bv[7];
        if (RELU) {
            v0 = fmaxf(v0, 0.f); v1 = fmaxf(v1, 0.f); v2 = fmaxf(v2, 0.f); v3 = fmaxf(v3, 0.f);
            v4 = fmaxf(v4, 0.f); v5 = fmaxf(v5, 0.f); v6 = fmaxf(v6, 0.f); v7 = fmaxf(v7, 0.f);
        }
        r0.x = v0; r0.y = v1; r0.z = v2; r0.w = v3;
        r1.x = v4; r1.y = v5; r1.z = v6; r1.w = v7;
        *(float4*)crow = r0;
        *(float4*)(crow + 4) = r1;
    }
}

// ---------------- time embedding: sinusoid + MLP -> g_comb[:, 0:128] ----------------
__global__ void __launch_bounds__(256) time_kernel(const int* __restrict__ ts,
                                                   const float* __restrict__ w1,
                                                   const float* __restrict__ b1,
                                                   const float* __restrict__ w2,
                                                   const float* __restrict__ b2) {
    __shared__ float te[128];
    __shared__ float hid[256];
    const int b = blockIdx.x, t = threadIdx.x;
    const float tf = (float)ts[b];
    if (t < 128) {
        int i = t & 63;
        float freq = expf(-0.14391156831212787f * (float)i);  // log(10000)/64
        float arg = tf * freq;
        te[t] = (t < 64) ? cosf(arg) : sinf(arg);
    }
    __syncthreads();
    float a = b1[t];
    for (int i = 0; i < 128; i++) a = fmaf(te[i], w1[i * 256 + t], a);
    hid[t] = siluf(a);
    __syncthreads();
    if (t < 128) {
        float a2 = b2[t];
        for (int i = 0; i < 256; i++) a2 = fmaf(hid[i], w2[i * 128 + t], a2);
        g_comb[(size_t)b * 256 + t] = a2;
    }
}

// ---------------- condition MLP: [B,S,6] -> g_h [B*S,128] ----------------
__global__ void __launch_bounds__(128) cond_kernel(const float* __restrict__ cond,
                                                   const float* __restrict__ w1,
                                                   const float* __restrict__ b1,
                                                   const float* __restrict__ w2,
                                                   const float* __restrict__ b2) {
    __shared__ float sw1[6 * 64];
    __shared__ float sb1[64];
    __shared__ float sw2[64 * 128];
    __shared__ float sb2[128];
    const int b = blockIdx.x, t = threadIdx.x;
    for (int i = t; i < 6 * 64; i += 128) sw1[i] = w1[i];
    if (t < 64) sb1[t] = b1[t];
    for (int i = t; i < 64 * 128; i += 128) sw2[i] = w2[i];
    sb2[t] = b2[t];
    __syncthreads();

    float c[6];
    const float* cp = cond + ((size_t)b * 128 + t) * 6;
#pragma unroll
    for (int i = 0; i < 6; i++) c[i] = cp[i];

    float hid[64];
#pragma unroll
    for (int j = 0; j < 64; j++) {
        float a = sb1[j];
#pragma unroll
        for (int i = 0; i < 6; i++) a = fmaf(c[i], sw1[i * 64 + j], a);
        hid[j] = siluf(a);
    }
    float* op = g_h + ((size_t)b * 128 + t) * 128;
    for (int d = 0; d < 128; d++) {
        float a = sb2[d];
#pragma unroll
        for (int j = 0; j < 64; j++) a = fmaf(hid[j], sw2[j * 128 + d], a);
        op[d] = siluf(a);
    }
}

// ---------------- attention: one CTA per (b, head), thread = query row ----------------
__global__ void __launch_bounds__(128) attn_kernel() {
    __shared__ float4 ks[128][8];
    __shared__ float4 vs[128][8];
    const int b = blockIdx.x >> 2;
    const int hd = blockIdx.x & 3;
    const int t = threadIdx.x;
    const float* rowp = g_qkv + ((size_t)b * 128 + t) * 384;
#pragma unroll
    for (int c = 0; c < 8; c++) ks[t][c] = *(const float4*)(rowp + 128 + hd * 32 + c * 4);
#pragma unroll
    for (int c = 0; c < 8; c++) vs[t][c] = *(const float4*)(rowp + 256 + hd * 32 + c * 4);
    float q[32];
#pragma unroll
    for (int c = 0; c < 8; c++) *(float4*)&q[c * 4] = *(const float4*)(rowp + hd * 32 + c * 4);
    __syncthreads();

    const float scale = 0.17677669529663687f;  // 1/sqrt(32)
    float m = -1e30f;
    for (int j = 0; j < 128; j++) {
        float d = 0.f;
#pragma unroll
        for (int c = 0; c < 8; c++) {
            float4 kv = ks[j][c];
            d = fmaf(q[c * 4 + 0], kv.x, d);
            d = fmaf(q[c * 4 + 1], kv.y, d);
            d = fmaf(q[c * 4 + 2], kv.z, d);
            d = fmaf(q[c * 4 + 3], kv.w, d);
        }
        m = fmaxf(m, d * scale);
    }
    float l = 0.f;
    float acc[32];
#pragma unroll
    for (int i = 0; i < 32; i++) acc[i] = 0.f;
    for (int j = 0; j < 128; j++) {
        float d = 0.f;
#pragma unroll
        for (int c = 0; c < 8; c++) {
            float4 kv = ks[j][c];
            d = fmaf(q[c * 4 + 0], kv.x, d);
            d = fmaf(q[c * 4 + 1], kv.y, d);
            d = fmaf(q[c * 4 + 2], kv.z, d);
            d = fmaf(q[c * 4 + 3], kv.w, d);
        }
        float e = __expf(d * scale - m);
        l += e;
#pragma unroll
        for (int c = 0; c < 8; c++) {
            float4 vv = vs[j][c];
            acc[c * 4 + 0] = fmaf(e, vv.x, acc[c * 4 + 0]);
            acc[c * 4 + 1] = fmaf(e, vv.y, acc[c * 4 + 1]);
            acc[c * 4 + 2] = fmaf(e, vv.z, acc[c * 4 + 2]);
            acc[c * 4 + 3] = fmaf(e, vv.w, acc[c * 4 + 3]);
        }
    }
    const float inv = 1.f / l;
    float* op = g_attn + ((size_t)b * 128 + t) * 128 + hd * 32;
#pragma unroll
    for (int c = 0; c < 8; c++) {
        float4 w;
        w.x = acc[c * 4 + 0] * inv;
        w.y = acc[c * 4 + 1] * inv;
        w.z = acc[c * 4 + 2] * inv;
        w.w = acc[c * 4 + 3] * inv;
        *(float4*)(op + c * 4) = w;
    }
}

// ---------------- residual + LayerNorm (in place on g_h): h = LN(h + o) ----------------
__global__ void __launch_bounds__(256) lnres_kernel(const float* __restrict__ o,
                                                    const float* __restrict__ gma,
                                                    const float* __restrict__ bta) {
    const int lane = threadIdx.x & 31;
    const int warp = threadIdx.x >> 5;
    const size_t row = (size_t)blockIdx.x * 8 + warp;
    float4 hv = *(float4*)(g_h + row * 128 + lane * 4);
    float4 ov = *(const float4*)(o + row * 128 + lane * 4);
    float x0 = hv.x + ov.x, x1 = hv.y + ov.y, x2 = hv.z + ov.z, x3 = hv.w + ov.w;
    float s = x0 + x1 + x2 + x3;
#pragma unroll
    for (int d = 16; d; d >>= 1) s += __shfl_xor_sync(0xffffffffu, s, d);
    float mean = s * (1.f / 128.f);
    float c0 = x0 - mean, c1 = x1 - mean, c2 = x2 - mean, c3 = x3 - mean;
    float v = c0 * c0 + c1 * c1 + c2 * c2 + c3 * c3;
#pragma unroll
    for (int d = 16; d; d >>= 1) v += __shfl_xor_sync(0xffffffffu, v, d);
    float rs = rsqrtf(v * (1.f / 128.f) + 1e-5f);
    float4 gv = *(const float4*)(gma + lane * 4);
    float4 bv = *(const float4*)(bta + lane * 4);
    float4 r;
    r.x = fmaf(gv.x, c0 * rs, bv.x);
    r.y = fmaf(gv.y, c1 * rs, bv.y);
    r.z = fmaf(gv.z, c2 * rs, bv.z);
    r.w = fmaf(gv.w, c3 * rs, bv.w);
    *(float4*)(g_h + row * 128 + lane * 4) = r;
}

// ---------------- mean pool over seq -> g_comb[:, 128:256] ----------------
__global__ void __launch_bounds__(128) pool_kernel() {
    const int b = blockIdx.x, d = threadIdx.x;
    const float* p = g_h + (size_t)b * 128 * 128 + d;
    float s = 0.f;
    for (int j = 0; j < 128; j++) s += p[j * 128];
    g_comb[(size_t)b * 256 + 128 + d] = s * (1.f / 128.f);
}

// ---------------- mixture weights -> g_mw ----------------
__global__ void __launch_bounds__(128) mw_kernel(const float* __restrict__ w1,
                                                 const float* __restrict__ b1,
                                                 const float* __restrict__ w2,
                                                 const float* __restrict__ b2) {
    __shared__ float sc[256];
    __shared__ float hid[128];
    __shared__ float lg[4];
    const int b = blockIdx.x, t = threadIdx.x;
    sc[t] = g_comb[(size_t)b * 256 + t];
    sc[128 + t] = g_comb[(size_t)b * 256 + 128 + t];
    __syncthreads();
    float a = b1[t];
    for (int i = 0; i < 256; i++) a = fmaf(sc[i], w1[i * 128 + t], a);
    hid[t] = siluf(a);
    __syncthreads();
    if (t < 4) {
        float a2 = b2[t];
        for (int j = 0; j < 128; j++) a2 = fmaf(hid[j], w2[j * 4 + t], a2);
        lg[t] = a2;
    }
    __syncthreads();
    if (t == 0) {
        float m = fmaxf(fmaxf(lg[0], lg[1]), fmaxf(lg[2], lg[3]));
        float e0 = __expf(lg[0] - m), e1 = __expf(lg[1] - m);
        float e2 = __expf(lg[2] - m), e3 = __expf(lg[3] - m);
        float inv = 1.f / (e0 + e1 + e2 + e3);
        g_mw[(size_t)b * 4 + 0] = e0 * inv;
        g_mw[(size_t)b * 4 + 1] = e1 * inv;
        g_mw[(size_t)b * 4 + 2] = e2 * inv;
        g_mw[(size_t)b * 4 + 3] = e3 * inv;
    }
}

// ---------------- pack s_w1[k][2+i][j] -> g_sw1p[i][k*128+j] ----------------
__global__ void __launch_bounds__(256) pack_kernel(const float* __restrict__ sw1) {
    int idx = blockIdx.x * 256 + threadIdx.x;  // < 256*512
    int i = idx >> 9;
    int r = idx & 511;
    int k = r >> 7, j = r & 127;
    g_sw1p[idx] = sw1[((size_t)k * 258 + 2 + i) * 128 + j];
}

// ---------------- students + mixture combine -> output [B,2,S] ----------------
__global__ void __launch_bounds__(128) student_kernel(const float* __restrict__ x,
                                                      const float* __restrict__ sw1,
                                                      const float* __restrict__ sw2,
                                                      const float* __restrict__ sb2,
                                                      float* __restrict__ out) {
    __shared__ float sb[512], w0[512], w1s[512], s2a[512], s2b[512];
    __shared__ float smw[4], sbias2[8];
    const int b = blockIdx.x, t = threadIdx.x;
    for (int i = t; i < 512; i += 128) {
        sb[i] = g_base[(size_t)b * 512 + i];
        int k = i >> 7, j = i & 127;
        w0[i] = sw1[((size_t)k * 258 + 0) * 128 + j];
        w1s[i] = sw1[((size_t)k * 258 + 1) * 128 + j];
        s2a[i] = sw2[i * 2 + 0];
        s2b[i] = sw2[i * 2 + 1];
    }
    if (t < 4) smw[t] = g_mw[(size_t)b * 4 + t];
    if (t < 8) sbias2[t] = sb2[t];
    __syncthreads();

    const float x0 = x[(size_t)b * 256 + t];
    const float x1 = x[(size_t)b * 256 + 128 + t];
    float o0 = 0.f, o1 = 0.f;
#pragma unroll
    for (int k = 0; k < 4; k++) {
        float a0 = 0.f, a1 = 0.f;
        for (int j = 0; j < 128; j++) {
            int idx = k * 128 + j;
            float hv = tanh_fast(fmaf(x1, w1s[idx], fmaf(x0, w0[idx], sb[idx])));
            a0 = fmaf(hv, s2a[idx], a0);
            a1 = fmaf(hv, s2b[idx], a1);
        }
        float wk = smw[k];
        o0 = fmaf(wk, a0 + sbias2[k * 2 + 0], o0);
        o1 = fmaf(wk, a1 + sbias2[k * 2 + 1], o1);
    }
    out[(size_t)b * 256 + t] = o0;
    out[(size_t)b * 256 + 128 + t] = o1;
}

// ---------------- launcher ----------------
extern "C" void kernel_launch(void* const* d_in, const int* in_sizes, int n_in,
                              void* d_out, int out_size) {
    const float* x    = (const float*)d_in[0];
    const int*   ts   = (const int*)d_in[1];
    const float* cond = (const float*)d_in[2];
    const float* t_w1 = (const float*)d_in[3];
    const float* t_b1 = (const float*)d_in[4];
    const float* t_w2 = (const float*)d_in[5];
    const float* t_b2 = (const float*)d_in[6];
    const float* c_w1 = (const float*)d_in[7];
    const float* c_b1 = (const float*)d_in[8];
    const float* c_w2 = (const float*)d_in[9];
    const float* c_b2 = (const float*)d_in[10];
    const float* wqkv = (const float*)d_in[11];
    const float* bqkv = (const float*)d_in[12];
    const float* wo   = (const float*)d_in[13];
    const float* bo   = (const float*)d_in[14];
    const float* ln1g = (const float*)d_in[15];
    const float* ln1b = (const float*)d_in[16];
    const float* ffw1 = (const float*)d_in[17];
    const float* ffb1 = (const float*)d_in[18];
    const float* ffw2 = (const float*)d_in[19];
    const float* ffb2 = (const float*)d_in[20];
    const float* ln2g = (const float*)d_in[21];
    const float* ln2b = (const float*)d_in[22];
    const float* mww1 = (const float*)d_in[23];
    const float* mwb1 = (const float*)d_in[24];
    const float* mww2 = (const float*)d_in[25];
    const float* mwb2 = (const float*)d_in[26];
    const float* sw1  = (const float*)d_in[27];
    const float* sb1  = (const float*)d_in[28];
    const float* sw2  = (const float*)d_in[29];
    const float* sb2  = (const float*)d_in[30];
    float* out = (float*)d_out;

    float *gh, *gqkv, *gattn, *gcomb, *gbase, *gsw1p;
    cudaGetSymbolAddress((void**)&gh, g_h);
    cudaGetSymbolAddress((void**)&gqkv, g_qkv);
    cudaGetSymbolAddress((void**)&gattn, g_attn);
    cudaGetSymbolAddress((void**)&gcomb, g_comb);
    cudaGetSymbolAddress((void**)&gbase, g_base);
    cudaGetSymbolAddress((void**)&gsw1p, g_sw1p);

    time_kernel<<<B_, 256>>>(ts, t_w1, t_b1, t_w2, t_b2);
    cond_kernel<<<B_, 128>>>(cond, c_w1, c_b1, c_w2, c_b2);

    for (int l = 0; l < 2; l++) {
        // qkv = h @ wqkv[l] + b      [M,128]@[128,384]
        gemm64<0><<<dim3(384 / 64, MROWS / 64), 64>>>(gh, wqkv + (size_t)l * 128 * 384,
                                                      bqkv + l * 384, gqkv, MROWS, 384, 128);
        attn_kernel<<<B_ * H_, 128>>>();
        // o-proj: attn @ wo[l] + b   [M,128]@[128,128] -> g_qkv reused as [M,128]
        gemm64<0><<<dim3(2, MROWS / 64), 64>>>(gattn, wo + (size_t)l * 128 * 128,
                                               bo + l * 128, gqkv, MROWS, 128, 128);
        lnres_kernel<<<MROWS / 8, 256>>>(gqkv, ln1g + l * 128, ln1b + l * 128);
        // ffn1: relu(h @ w1 + b)     [M,128]@[128,256] -> g_qkv as [M,256]
        gemm64<1><<<dim3(4, MROWS / 64), 64>>>(gh, ffw1 + (size_t)l * 128 * 256,
                                               ffb1 + l * 256, gqkv, MROWS, 256, 128);
        // ffn2:                      [M,256]@[256,128] -> g_attn
        gemm64<0><<<dim3(2, MROWS / 64), 64>>>(gqkv, ffw2 + (size_t)l * 256 * 128,
                                               ffb2 + l * 128, gattn, MROWS, 128, 256);
        lnres_kernel<<<MROWS / 8, 256>>>(gattn, ln2g + l * 128, ln2b + l * 128);
    }

    pool_kernel<<<B_, 128>>>();
    mw_kernel<<<B_, 128>>>(mww1, mwb1, mww2, mwb2);
    pack_kernel<<<512, 256>>>(sw1);
    // base = combined @ packed_sw1 + s_b1   [4096,256]@[256,512]
    gemm64<0><<<dim3(8, B_ / 64), 64>>>(gcomb, gsw1p, sb1, gbase, B_, 512, 256);
    student_kernel<<<B_, 128>>>(x, sw1, sw2, sb2, out);
}

// round 5
// speedup vs baseline: 1.5890x; 1.5890x over previous
#include <cuda_runtime.h>
#include <math.h>

#define B_    4096
#define S_    128
#define D_    128
#define H_    4
#define FF_   256
#define K_    4
#define MROWS (B_ * S_)   // 524288

// ---------------- global scratch (no allocations allowed) ----------------
__device__ float g_h[(size_t)MROWS * 128];     // activations [B*S,128]
__device__ float g_qkv[(size_t)MROWS * 384];   // qkv / ffn-hidden
__device__ float g_attn[(size_t)MROWS * 128];  // attention out
__device__ float g_ch1[(size_t)MROWS * 64];    // cond MLP hidden
__device__ float g_comb[(size_t)B_ * 256];     // [time_emb | cond_emb]
__device__ float g_mw[(size_t)B_ * 4];         // mixture weights
__device__ float g_base[(size_t)B_ * 512];     // folded student hidden base
__device__ float g_sw1p[256 * 512];            // packed s_w1[:,2:,:] -> [256,512]

typedef unsigned long long u64t;

__device__ __forceinline__ float siluf(float x) { return x / (1.f + __expf(-x)); }
__device__ __forceinline__ float tanh_fast(float x) { return 1.f - 2.f / (__expf(2.f * x) + 1.f); }

// packed f32x2 FMA (Blackwell): d.lo += a.lo*b.lo ; d.hi += a.hi*b.hi
__device__ __forceinline__ void fma2(u64t& d, u64t a, u64t b) {
    asm("fma.rn.f32x2 %0, %1, %2, %0;" : "+l"(d) : "l"(a), "l"(b));
}
__device__ __forceinline__ u64t pk2(float x, float y) {
    u64t r; asm("mov.b64 %0, {%1, %2};" : "=l"(r) : "f"(x), "f"(y)); return r;
}
__device__ __forceinline__ float2 up2(u64t v) {
    float2 r; asm("mov.b64 {%0, %1}, %2;" : "=f"(r.x), "=f"(r.y) : "l"(v)); return r;
}

// ---------------- tiled SGEMM with f32x2 inner loop ----------------
// C[M,N] = A[M,K] @ B[K,N] + bias, BM=64 BN=128 BK=32, 128 threads, 8x8 micro-tile.
// MODE: 0 plain, 1 relu, 2 residual+LayerNorm (requires N==128, grid.x==1), 3 silu.
template <int MODE>
__global__ void __launch_bounds__(128) gemm128(const float* __restrict__ A,
                                               const float* __restrict__ Bm,
                                               const float* __restrict__ bias,
                                               const float* __restrict__ res,
                                               const float* __restrict__ gma,
                                               const float* __restrict__ bta,
                                               float* __restrict__ C,
                                               int M, int N, int K) {
    __shared__ float As[32][68];   // transposed A tile (padded)
    __shared__ float Bs[32][128];
    const int tid = threadIdx.x;
    const int bm = blockIdx.y * 64;
    const int bn = blockIdx.x * 128;
    const int tx = tid & 15;        // 16 col-groups of 8
    const int ty = tid >> 4;        // 8 row-groups of 8

    u64t acc[8][4];
#pragma unroll
    for (int i = 0; i < 8; i++)
#pragma unroll
        for (int j = 0; j < 4; j++) acc[i][j] = 0ULL;

    const int a_k = (tid & 7) * 4;
    const int a_r0 = tid >> 3;       // 0..15
    const int b_w = tid >> 5;        // 0..3
    const int b_l = (tid & 31) * 4;  // 0..124

    for (int kk = 0; kk < K; kk += 32) {
        // A tile: load coalesced, store transposed
#pragma unroll
        for (int c = 0; c < 4; c++) {
            int row = a_r0 + c * 16;
            float4 v = *(const float4*)(A + (size_t)(bm + row) * K + kk + a_k);
            As[a_k + 0][row] = v.x;
            As[a_k + 1][row] = v.y;
            As[a_k + 2][row] = v.z;
            As[a_k + 3][row] = v.w;
        }
        // B tile
#pragma unroll
        for (int c = 0; c < 8; c++) {
            int row = b_w * 8 + c;
            *(float4*)&Bs[row][b_l] = *(const float4*)(Bm + (size_t)(kk + row) * N + bn + b_l);
        }
        __syncthreads();
#pragma unroll 8
        for (int k = 0; k < 32; k++) {
            float4 aa0 = *(const float4*)&As[k][ty * 8];
            float4 aa1 = *(const float4*)&As[k][ty * 8 + 4];
            u64t a2[8];
            a2[0] = pk2(aa0.x, aa0.x); a2[1] = pk2(aa0.y, aa0.y);
            a2[2] = pk2(aa0.z, aa0.z); a2[3] = pk2(aa0.w, aa0.w);
            a2[4] = pk2(aa1.x, aa1.x); a2[5] = pk2(aa1.y, aa1.y);
            a2[6] = pk2(aa1.z, aa1.z); a2[7] = pk2(aa1.w, aa1.w);
            ulonglong2 bb0 = *(const ulonglong2*)&Bs[k][tx * 8];
            ulonglong2 bb1 = *(const ulonglong2*)&Bs[k][tx * 8 + 4];
            u64t bv[4] = {bb0.x, bb0.y, bb1.x, bb1.y};
#pragma unroll
            for (int i = 0; i < 8; i++) {
                fma2(acc[i][0], a2[i], bv[0]);
                fma2(acc[i][1], a2[i], bv[1]);
                fma2(acc[i][2], a2[i], bv[2]);
                fma2(acc[i][3], a2[i], bv[3]);
            }
        }
        __syncthreads();
    }

    float bvv[8];
#pragma unroll
    for (int j = 0; j < 8; j++) bvv[j] = bias[bn + tx * 8 + j];

    float v[8][8];
#pragma unroll
    for (int i = 0; i < 8; i++)
#pragma unroll
        for (int j = 0; j < 4; j++) {
            float2 p = up2(acc[i][j]);
            v[i][2 * j] = p.x + bvv[2 * j];
            v[i][2 * j + 1] = p.y + bvv[2 * j + 1];
        }

    if (MODE == 2) {
        // residual + LayerNorm over the 128-wide row (16 tx lanes per row)
#pragma unroll
        for (int i = 0; i < 8; i++) {
            int row = bm + ty * 8 + i;
            float4 r0 = *(const float4*)(res + (size_t)row * 128 + tx * 8);
            float4 r1 = *(const float4*)(res + (size_t)row * 128 + tx * 8 + 4);
            v[i][0] += r0.x; v[i][1] += r0.y; v[i][2] += r0.z; v[i][3] += r0.w;
            v[i][4] += r1.x; v[i][5] += r1.y; v[i][6] += r1.z; v[i][7] += r1.w;
        }
        float s[8];
#pragma unroll
        for (int i = 0; i < 8; i++) {
            s[i] = v[i][0] + v[i][1] + v[i][2] + v[i][3] + v[i][4] + v[i][5] + v[i][6] + v[i][7];
        }
#pragma unroll
        for (int m = 1; m < 16; m <<= 1)
#pragma unroll
            for (int i = 0; i < 8; i++) s[i] += __shfl_xor_sync(0xffffffffu, s[i], m, 16);
        float var[8];
#pragma unroll
        for (int i = 0; i < 8; i++) {
            float mean = s[i] * (1.f / 128.f);
            float acc2 = 0.f;
#pragma unroll
            for (int j = 0; j < 8; j++) { v[i][j] -= mean; acc2 += v[i][j] * v[i][j]; }
            var[i] = acc2;
        }
#pragma unroll
        for (int m = 1; m < 16; m <<= 1)
#pragma unroll
            for (int i = 0; i < 8; i++) var[i] += __shfl_xor_sync(0xffffffffu, var[i], m, 16);
        float4 g0 = *(const float4*)(gma + tx * 8);
        float4 g1 = *(const float4*)(gma + tx * 8 + 4);
        float4 t0 = *(const float4*)(bta + tx * 8);
        float4 t1 = *(const float4*)(bta + tx * 8 + 4);
#pragma unroll
        for (int i = 0; i < 8; i++) {
            float rs = rsqrtf(var[i] * (1.f / 128.f) + 1e-5f);
            int row = bm + ty * 8 + i;
            float4 o0, o1;
            o0.x = fmaf(g0.x, v[i][0] * rs, t0.x);
            o0.y = fmaf(g0.y, v[i][1] * rs, t0.y);
            o0.z = fmaf(g0.z, v[i][2] * rs, t0.z);
            o0.w = fmaf(g0.w, v[i][3] * rs, t0.w);
            o1.x = fmaf(g1.x, v[i][4] * rs, t1.x);
            o1.y = fmaf(g1.y, v[i][5] * rs, t1.y);
            o1.z = fmaf(g1.z, v[i][6] * rs, t1.z);
            o1.w = fmaf(g1.w, v[i][7] * rs, t1.w);
            *(float4*)(C + (size_t)row * 128 + tx * 8) = o0;
            *(float4*)(C + (size_t)row * 128 + tx * 8 + 4) = o1;
        }
    } else {
#pragma unroll
        for (int i = 0; i < 8; i++) {
#pragma unroll
            for (int j = 0; j < 8; j++) {
                if (MODE == 1) v[i][j] = fmaxf(v[i][j], 0.f);
                if (MODE == 3) v[i][j] = siluf(v[i][j]);
            }
            int row = bm + ty * 8 + i;
            float4 o0, o1;
            o0.x = v[i][0]; o0.y = v[i][1]; o0.z = v[i][2]; o0.w = v[i][3];
            o1.x = v[i][4]; o1.y = v[i][5]; o1.z = v[i][6]; o1.w = v[i][7];
            *(float4*)(C + (size_t)row * N + bn + tx * 8) = o0;
            *(float4*)(C + (size_t)row * N + bn + tx * 8 + 4) = o1;
        }
    }
}

// ---------------- time embedding: sinusoid + MLP -> g_comb[:, 0:128] ----------------
__global__ void __launch_bounds__(256) time_kernel(const int* __restrict__ ts,
                                                   const float* __restrict__ w1,
                                                   const float* __restrict__ b1,
                                                   const float* __restrict__ w2,
                                                   const float* __restrict__ b2) {
    __shared__ float te[128];
    __shared__ float hid[256];
    const int b = blockIdx.x, t = threadIdx.x;
    const float tf = (float)ts[b];
    if (t < 128) {
        int i = t & 63;
        float freq = expf(-0.14391156831212787f * (float)i);  // log(10000)/64
        float arg = tf * freq;
        te[t] = (t < 64) ? cosf(arg) : sinf(arg);
    }
    __syncthreads();
    float a = b1[t];
    for (int i = 0; i < 128; i++) a = fmaf(te[i], w1[i * 256 + t], a);
    hid[t] = siluf(a);
    __syncthreads();
    if (t < 128) {
        float a2 = b2[t];
        for (int i = 0; i < 256; i++) a2 = fmaf(hid[i], w2[i * 128 + t], a2);
        g_comb[(size_t)b * 256 + t] = a2;
    }
}

// ---------------- cond layer1: [B*S,6] -> silu -> g_ch1 [B*S,64] ----------------
__global__ void __launch_bounds__(256) condh1_kernel(const float* __restrict__ cond,
                                                     const float* __restrict__ w1,
                                                     const float* __restrict__ b1) {
    const size_t row = (size_t)blockIdx.x * 32 + (threadIdx.x >> 3);
    const int dg = threadIdx.x & 7;
    const float* cp = cond + row * 6;
    float c0 = cp[0], c1 = cp[1], c2 = cp[2], c3 = cp[3], c4 = cp[4], c5 = cp[5];
    float o[8];
#pragma unroll
    for (int j = 0; j < 8; j++) {
        int d = dg * 8 + j;
        float a = b1[d];
        a = fmaf(c0, w1[0 * 64 + d], a);
        a = fmaf(c1, w1[1 * 64 + d], a);
        a = fmaf(c2, w1[2 * 64 + d], a);
        a = fmaf(c3, w1[3 * 64 + d], a);
        a = fmaf(c4, w1[4 * 64 + d], a);
        a = fmaf(c5, w1[5 * 64 + d], a);
        o[j] = siluf(a);
    }
    float4 v0, v1;
    v0.x = o[0]; v0.y = o[1]; v0.z = o[2]; v0.w = o[3];
    v1.x = o[4]; v1.y = o[5]; v1.z = o[6]; v1.w = o[7];
    *(float4*)(g_ch1 + row * 64 + dg * 8) = v0;
    *(float4*)(g_ch1 + row * 64 + dg * 8 + 4) = v1;
}

// ---------------- attention: one CTA per (b, head), thread = query row ----------------
// dynamic smem: ks[128][32] | vs[128][32] | sc[128][129]
#define ATTN_SMEM ((8192 + 128 * 129) * 4)
__global__ void __launch_bounds__(128) attn_kernel() {
    extern __shared__ float smem[];
    float (*ks)[32] = (float(*)[32])smem;
    float (*vs)[32] = (float(*)[32])(smem + 4096);
    float (*sc)[129] = (float(*)[129])(smem + 8192);

    const int b = blockIdx.x >> 2;
    const int hd = blockIdx.x & 3;
    const int t = threadIdx.x;
    const float* rowp = g_qkv + ((size_t)b * 128 + t) * 384;
#pragma unroll
    for (int c = 0; c < 8; c++)
        *(float4*)&ks[t][c * 4] = *(const float4*)(rowp + 128 + hd * 32 + c * 4);
#pragma unroll
    for (int c = 0; c < 8; c++)
        *(float4*)&vs[t][c * 4] = *(const float4*)(rowp + 256 + hd * 32 + c * 4);
    u64t q2[16];
#pragma unroll
    for (int c = 0; c < 8; c++) {
        ulonglong2 qv = *(const ulonglong2*)(rowp + hd * 32 + c * 4);
        q2[2 * c] = qv.x;
        q2[2 * c + 1] = qv.y;
    }
    __syncthreads();

    const float scale = 0.17677669529663687f;  // 1/sqrt(32)
    float m = -1e30f;
    for (int j = 0; j < 128; j++) {
        u64t d2 = 0ULL;
        const ulonglong2* kp = (const ulonglong2*)&ks[j][0];
#pragma unroll
        for (int c = 0; c < 8; c++) {
            ulonglong2 kv = kp[c];
            fma2(d2, q2[2 * c], kv.x);
            fma2(d2, q2[2 * c + 1], kv.y);
        }
        float2 dp = up2(d2);
        float s = (dp.x + dp.y) * scale;
        sc[t][j] = s;
        m = fmaxf(m, s);
    }
    float l = 0.f;
    u64t acc2[16];
#pragma unroll
    for (int i = 0; i < 16; i++) acc2[i] = 0ULL;
    for (int j = 0; j < 128; j++) {
        float e = __expf(sc[t][j] - m);
        l += e;
        u64t e2 = pk2(e, e);
        const ulonglong2* vp = (const ulonglong2*)&vs[j][0];
#pragma unroll
        for (int c = 0; c < 8; c++) {
            ulonglong2 vv = vp[c];
            fma2(acc2[2 * c], e2, vv.x);
            fma2(acc2[2 * c + 1], e2, vv.y);
        }
    }
    const float inv = 1.f / l;
    float* op = g_attn + ((size_t)b * 128 + t) * 128 + hd * 32;
#pragma unroll
    for (int c = 0; c < 16; c++) {
        float2 p = up2(acc2[c]);
        p.x *= inv;
        p.y *= inv;
        *(float2*)(op + 2 * c) = p;
    }
}

// ---------------- mean pool over seq -> g_comb[:, 128:256] ----------------
__global__ void __launch_bounds__(128) pool_kernel() {
    const int b = blockIdx.x, d = threadIdx.x;
    const float* p = g_h + (size_t)b * 128 * 128 + d;
    float s = 0.f;
    for (int j = 0; j < 128; j++) s += p[j * 128];
    g_comb[(size_t)b * 256 + 128 + d] = s * (1.f / 128.f);
}

// ---------------- mixture weights -> g_mw ----------------
__global__ void __launch_bounds__(128) mw_kernel(const float* __restrict__ w1,
                                                 const float* __restrict__ b1,
                                                 const float* __restrict__ w2,
                                                 const float* __restrict__ b2) {
    __shared__ float scm[256];
    __shared__ float hid[128];
    __shared__ float lg[4];
    const int b = blockIdx.x, t = threadIdx.x;
    scm[t] = g_comb[(size_t)b * 256 + t];
    scm[128 + t] = g_comb[(size_t)b * 256 + 128 + t];
    __syncthreads();
    float a = b1[t];
    for (int i = 0; i < 256; i++) a = fmaf(scm[i], w1[i * 128 + t], a);
    hid[t] = siluf(a);
    __syncthreads();
    if (t < 4) {
        float a2 = b2[t];
        for (int j = 0; j < 128; j++) a2 = fmaf(hid[j], w2[j * 4 + t], a2);
        lg[t] = a2;
    }
    __syncthreads();
    if (t == 0) {
        float mm = fmaxf(fmaxf(lg[0], lg[1]), fmaxf(lg[2], lg[3]));
        float e0 = __expf(lg[0] - mm), e1 = __expf(lg[1] - mm);
        float e2 = __expf(lg[2] - mm), e3 = __expf(lg[3] - mm);
        float inv = 1.f / (e0 + e1 + e2 + e3);
        g_mw[(size_t)b * 4 + 0] = e0 * inv;
        g_mw[(size_t)b * 4 + 1] = e1 * inv;
        g_mw[(size_t)b * 4 + 2] = e2 * inv;
        g_mw[(size_t)b * 4 + 3] = e3 * inv;
    }
}

// ---------------- pack s_w1[k][2+i][j] -> g_sw1p[i][k*128+j] ----------------
__global__ void __launch_bounds__(256) pack_kernel(const float* __restrict__ sw1) {
    int idx = blockIdx.x * 256 + threadIdx.x;  // < 256*512
    int i = idx >> 9;
    int r = idx & 511;
    int k = r >> 7, j = r & 127;
    g_sw1p[idx] = sw1[((size_t)k * 258 + 2 + i) * 128 + j];
}

// ---------------- students + mixture combine -> output [B,2,S] ----------------
__global__ void __launch_bounds__(128) student_kernel(const float* __restrict__ x,
                                                      const float* __restrict__ sw1,
                                                      const float* __restrict__ sw2,
                                                      const float* __restrict__ sb2,
                                                      float* __restrict__ out) {
    __shared__ float sb[512], w0[512], w1s[512], s2a[512], s2b[512];
    __shared__ float smw[4], sbias2[8];
    const int b = blockIdx.x, t = threadIdx.x;
    for (int i = t; i < 512; i += 128) {
        sb[i] = g_base[(size_t)b * 512 + i];
        int k = i >> 7, j = i & 127;
        w0[i] = sw1[((size_t)k * 258 + 0) * 128 + j];
        w1s[i] = sw1[((size_t)k * 258 + 1) * 128 + j];
        s2a[i] = sw2[i * 2 + 0];
        s2b[i] = sw2[i * 2 + 1];
    }
    if (t < 4) smw[t] = g_mw[(size_t)b * 4 + t];
    if (t < 8) sbias2[t] = sb2[t];
    __syncthreads();

    const float x0 = x[(size_t)b * 256 + t];
    const float x1 = x[(size_t)b * 256 + 128 + t];
    float o0 = 0.f, o1 = 0.f;
#pragma unroll
    for (int k = 0; k < 4; k++) {
        float a0 = 0.f, a1 = 0.f;
        for (int j = 0; j < 128; j++) {
            int idx = k * 128 + j;
            float hv = tanh_fast(fmaf(x1, w1s[idx], fmaf(x0, w0[idx], sb[idx])));
            a0 = fmaf(hv, s2a[idx], a0);
            a1 = fmaf(hv, s2b[idx], a1);
        }
        float wk = smw[k];
        o0 = fmaf(wk, a0 + sbias2[k * 2 + 0], o0);
        o1 = fmaf(wk, a1 + sbias2[k * 2 + 1], o1);
    }
    out[(size_t)b * 256 + t] = o0;
    out[(size_t)b * 256 + 128 + t] = o1;
}

// ---------------- launcher ----------------
extern "C" void kernel_launch(void* const* d_in, const int* in_sizes, int n_in,
                              void* d_out, int out_size) {
    const float* x    = (const float*)d_in[0];
    const int*   ts   = (const int*)d_in[1];
    const float* cond = (const float*)d_in[2];
    const float* t_w1 = (const float*)d_in[3];
    const float* t_b1 = (const float*)d_in[4];
    const float* t_w2 = (const float*)d_in[5];
    const float* t_b2 = (const float*)d_in[6];
    const float* c_w1 = (const float*)d_in[7];
    const float* c_b1 = (const float*)d_in[8];
    const float* c_w2 = (const float*)d_in[9];
    const float* c_b2 = (const float*)d_in[10];
    const float* wqkv = (const float*)d_in[11];
    const float* bqkv = (const float*)d_in[12];
    const float* wo   = (const float*)d_in[13];
    const float* bo   = (const float*)d_in[14];
    const float* ln1g = (const float*)d_in[15];
    const float* ln1b = (const float*)d_in[16];
    const float* ffw1 = (const float*)d_in[17];
    const float* ffb1 = (const float*)d_in[18];
    const float* ffw2 = (const float*)d_in[19];
    const float* ffb2 = (const float*)d_in[20];
    const float* ln2g = (const float*)d_in[21];
    const float* ln2b = (const float*)d_in[22];
    const float* mww1 = (const float*)d_in[23];
    const float* mwb1 = (const float*)d_in[24];
    const float* mww2 = (const float*)d_in[25];
    const float* mwb2 = (const float*)d_in[26];
    const float* sw1  = (const float*)d_in[27];
    const float* sb1  = (const float*)d_in[28];
    const float* sw2  = (const float*)d_in[29];
    const float* sb2  = (const float*)d_in[30];
    float* out = (float*)d_out;

    float *gh, *gqkv, *gattn, *gch1, *gcomb, *gbase, *gsw1p;
    cudaGetSymbolAddress((void**)&gh, g_h);
    cudaGetSymbolAddress((void**)&gqkv, g_qkv);
    cudaGetSymbolAddress((void**)&gattn, g_attn);
    cudaGetSymbolAddress((void**)&gch1, g_ch1);
    cudaGetSymbolAddress((void**)&gcomb, g_comb);
    cudaGetSymbolAddress((void**)&gbase, g_base);
    cudaGetSymbolAddress((void**)&gsw1p, g_sw1p);

    cudaFuncSetAttribute(attn_kernel, cudaFuncAttributeMaxDynamicSharedMemorySize, ATTN_SMEM);

    time_kernel<<<B_, 256>>>(ts, t_w1, t_b1, t_w2, t_b2);
    // cond MLP: layer1 small kernel, layer2 as GEMM with SiLU epilogue
    condh1_kernel<<<MROWS / 32, 256>>>(cond, c_w1, c_b1);
    gemm128<3><<<dim3(1, MROWS / 64), 128>>>(gch1, c_w2, c_b2, nullptr, nullptr, nullptr,
                                             gh, MROWS, 128, 64);

    for (int l = 0; l < 2; l++) {
        // qkv = h @ wqkv[l] + b   [M,128]@[128,384]
        gemm128<0><<<dim3(3, MROWS / 64), 128>>>(gh, wqkv + (size_t)l * 128 * 384,
                                                 bqkv + l * 384, nullptr, nullptr, nullptr,
                                                 gqkv, MROWS, 384, 128);
        attn_kernel<<<B_ * H_, 128, ATTN_SMEM>>>();
        // o-proj + residual + LN fused: h = LN(h + attn@wo + bo)
        gemm128<2><<<dim3(1, MROWS / 64), 128>>>(gattn, wo + (size_t)l * 128 * 128,
                                                 bo + l * 128, gh, ln1g + l * 128,
                                                 ln1b + l * 128, gh, MROWS, 128, 128);
        // ffn1: relu(h @ w1 + b)  [M,128]@[128,256]
        gemm128<1><<<dim3(2, MROWS / 64), 128>>>(gh, ffw1 + (size_t)l * 128 * 256,
                                                 ffb1 + l * 256, nullptr, nullptr, nullptr,
                                                 gqkv, MROWS, 256, 128);
        // ffn2 + residual + LN fused: h = LN(h + hid@w2 + b2)
        gemm128<2><<<dim3(1, MROWS / 64), 128>>>(gqkv, ffw2 + (size_t)l * 256 * 128,
                                                 ffb2 + l * 128, gh, ln2g + l * 128,
                                                 ln2b + l * 128, gh, MROWS, 128, 256);
    }

    pool_kernel<<<B_, 128>>>();
    mw_kernel<<<B_, 128>>>(mww1, mwb1, mww2, mwb2);
    pack_kernel<<<512, 256>>>(sw1);
    // base = combined @ packed_sw1 + s_b1   [4096,256]@[256,512]
    gemm128<0><<<dim3(4, B_ / 64), 128>>>(gcomb, gsw1p, sb1, nullptr, nullptr, nullptr,
                                          gbase, B_, 512, 256);
    student_kernel<<<B_, 128>>>(x, sw1, sw2, sb2, out);
}

// round 8
// speedup vs baseline: 1.8632x; 1.1726x over previous
#include <cuda_runtime.h>
#include <math.h>
#include <stdint.h>

#define B_    4096
#define MROWS (B_ * 128)   // 524288

// ---------------- global scratch ----------------
__device__ float g_h[(size_t)MROWS * 128];
__device__ float g_qkv[(size_t)MROWS * 384];
__device__ float g_attn[(size_t)MROWS * 128];
__device__ float g_ch1[(size_t)MROWS * 64];
__device__ float g_comb[(size_t)B_ * 256];
__device__ float g_mw[(size_t)B_ * 4];
__device__ float g_base[(size_t)B_ * 512];
__device__ float g_sw1p[256 * 512];   // folded student weight [256,512] row-major

typedef unsigned long long u64t;

__device__ __forceinline__ float siluf(float x) { return x / (1.f + __expf(-x)); }
__device__ __forceinline__ float tanh_fast(float x) { return 1.f - 2.f / (__expf(2.f * x) + 1.f); }
__device__ __forceinline__ void fma2(u64t& d, u64t a, u64t b) {
    asm("fma.rn.f32x2 %0, %1, %2, %0;" : "+l"(d) : "l"(a), "l"(b));
}
__device__ __forceinline__ u64t pk2(float x, float y) {
    u64t r; asm("mov.b64 %0, {%1, %2};" : "=l"(r) : "f"(x), "f"(y)); return r;
}
__device__ __forceinline__ float2 up2(u64t v) {
    float2 r; asm("mov.b64 {%0, %1}, %2;" : "=f"(r.x), "=f"(r.y) : "l"(v)); return r;
}
__device__ __forceinline__ uint32_t smem_u32(const void* p) {
    uint32_t a;
    asm("{ .reg .u64 t; cvta.to.shared.u64 t, %1; cvt.u32.u64 %0, t; }" : "=r"(a) : "l"(p));
    return a;
}

// ---- cp.async ----
__device__ __forceinline__ void cp16(uint32_t dst, const void* src) {
    asm volatile("cp.async.ca.shared.global [%0], [%1], 16;" :: "r"(dst), "l"(src));
}
__device__ __forceinline__ void cp_commit() { asm volatile("cp.async.commit_group;" ::: "memory"); }
template <int N>
__device__ __forceinline__ void cp_wait() { asm volatile("cp.async.wait_group %0;" :: "n"(N) : "memory"); }

// ---- tf32 mma.sync m16n8k8 ----
__device__ __forceinline__ void mma8(float* c, const uint32_t* a, uint32_t b0, uint32_t b1) {
    asm volatile(
        "mma.sync.aligned.m16n8k8.row.col.f32.tf32.tf32.f32 "
        "{%0,%1,%2,%3}, {%4,%5,%6,%7}, {%8,%9}, {%0,%1,%2,%3};"
        : "+f"(c[0]), "+f"(c[1]), "+f"(c[2]), "+f"(c[3])
        : "r"(a[0]), "r"(a[1]), "r"(a[2]), "r"(a[3]), "r"(b0), "r"(b1));
}

// split fp32 into tf32 hi + tf32 lo (3xTF32 compensation)
__device__ __forceinline__ void split_tf32(uint32_t raw, uint32_t& hi, uint32_t& lo) {
    float x = __uint_as_float(raw);
    float h, l;
    asm("cvt.rna.tf32.f32 %0, %1;" : "=f"(h) : "f"(x));
    float r = x - h;
    asm("cvt.rna.tf32.f32 %0, %1;" : "=f"(l) : "f"(r));
    hi = __float_as_uint(h);
    lo = __float_as_uint(l);
}

// ---------------- tf32 tensor GEMM (3xTF32) ----------------
// C[bm:bm+128, bn:bn+128] = A[128,Ktot] @ W[Ktot, ldb](cols bn..) + epilogue
// MODE: 0 bias, 1 relu, 2 residual+LayerNorm (N==128, grid.x==1, ldc==128), 3 silu
#define ASZ 18432      // 128 * 36 * 4
#define BSZ 17408      // 32 * 136 * 4
#define TG_SMEM (2 * ASZ + 2 * BSZ)   // 71680
template <int MODE>
__global__ void __launch_bounds__(128) tgemm(const float* __restrict__ A, int lda,
                                             const float* __restrict__ W, int ldb, int Ktot,
                                             const float* __restrict__ bias,
                                             const float* __restrict__ res,
                                             const float* __restrict__ gma,
                                             const float* __restrict__ bta,
                                             float* __restrict__ C, int ldc) {
    extern __shared__ char dsm[];
    const uint32_t sbase = smem_u32(dsm);
    const int t = threadIdx.x;
    const int w = t >> 5, lane = t & 31;
    const int g = lane >> 2, t4 = lane & 3;
    const int bn = blockIdx.x * 128, bm = blockIdx.y * 128;
    const int wrow = w * 32;

    float acc0[16][4], acc1[16][4];
#pragma unroll
    for (int j = 0; j < 16; j++)
#pragma unroll
        for (int q = 0; q < 4; q++) { acc0[j][q] = 0.f; acc1[j][q] = 0.f; }

    const int P = Ktot >> 5;

    // prologue: tile 0
    {
        const uint32_t as = sbase, bs = sbase + 2 * ASZ;
#pragma unroll
        for (int i = 0; i < 8; i++) {
            int idx = t + i * 128;
            int row = idx >> 3, c4 = (idx & 7) * 4;
            cp16(as + (uint32_t)(row * 36 + c4) * 4u, A + (size_t)(bm + row) * lda + c4);
        }
#pragma unroll
        for (int i = 0; i < 8; i++) {
            int idx = t + i * 128;
            int row = idx >> 5, c4 = (idx & 31) * 4;
            cp16(bs + (uint32_t)(row * 136 + c4) * 4u, W + (size_t)row * ldb + bn + c4);
        }
        cp_commit();
    }

    for (int p = 0; p < P; p++) {
        if (p + 1 < P) {
            const int buf = (p + 1) & 1;
            const uint32_t as = sbase + buf * ASZ, bs = sbase + 2 * ASZ + buf * BSZ;
            const int kof = (p + 1) * 32;
#pragma unroll
            for (int i = 0; i < 8; i++) {
                int idx = t + i * 128;
                int row = idx >> 3, c4 = (idx & 7) * 4;
                cp16(as + (uint32_t)(row * 36 + c4) * 4u,
                     A + (size_t)(bm + row) * lda + kof + c4);
            }
#pragma unroll
            for (int i = 0; i < 8; i++) {
                int idx = t + i * 128;
                int row = idx >> 5, c4 = (idx & 31) * 4;
                cp16(bs + (uint32_t)(row * 136 + c4) * 4u,
                     W + (size_t)(kof + row) * ldb + bn + c4);
            }
            cp_commit();
            cp_wait<1>();
        } else {
            cp_wait<0>();
        }
        __syncthreads();
        const uint32_t* Asu = (const uint32_t*)(dsm + (p & 1) * ASZ);
        const uint32_t* Bsu = (const uint32_t*)(dsm + 2 * ASZ + (p & 1) * BSZ);
#pragma unroll
        for (int ks = 0; ks < 4; ks++) {
            const int k0 = ks * 8;
            const int r = wrow + g;
            uint32_t a0h[4], a0l[4], a1h[4], a1l[4];
            split_tf32(Asu[(r) * 36 + k0 + t4],          a0h[0], a0l[0]);
            split_tf32(Asu[(r + 8) * 36 + k0 + t4],      a0h[1], a0l[1]);
            split_tf32(Asu[(r) * 36 + k0 + t4 + 4],      a0h[2], a0l[2]);
            split_tf32(Asu[(r + 8) * 36 + k0 + t4 + 4],  a0h[3], a0l[3]);
            split_tf32(Asu[(r + 16) * 36 + k0 + t4],     a1h[0], a1l[0]);
            split_tf32(Asu[(r + 24) * 36 + k0 + t4],     a1h[1], a1l[1]);
            split_tf32(Asu[(r + 16) * 36 + k0 + t4 + 4], a1h[2], a1l[2]);
            split_tf32(Asu[(r + 24) * 36 + k0 + t4 + 4], a1h[3], a1l[3]);
#pragma unroll
            for (int j = 0; j < 16; j++) {
                uint32_t b0h, b0l, b1h, b1l;
                split_tf32(Bsu[(k0 + t4) * 136 + j * 8 + g], b0h, b0l);
                split_tf32(Bsu[(k0 + t4 + 4) * 136 + j * 8 + g], b1h, b1l);
                mma8(acc0[j], a0h, b0h, b1h);
                mma8(acc0[j], a0l, b0h, b1h);
                mma8(acc0[j], a0h, b0l, b1l);
                mma8(acc1[j], a1h, b0h, b1h);
                mma8(acc1[j], a1l, b0h, b1h);
                mma8(acc1[j], a1h, b0l, b1l);
            }
        }
        __syncthreads();
    }

    // ---------------- epilogue ----------------
    float2 bias2[16];
#pragma unroll
    for (int j = 0; j < 16; j++) bias2[j] = *(const float2*)(bias + bn + j * 8 + 2 * t4);

    if (MODE == 2) {
#pragma unroll
        for (int i = 0; i < 2; i++) {
            float (*ac)[4] = i ? acc1 : acc0;
#pragma unroll
            for (int h = 0; h < 2; h++) {
                const int row = bm + wrow + i * 16 + h * 8 + g;
                const float* rp = res + (size_t)row * 128 + 2 * t4;
                float sum = 0.f;
#pragma unroll
                for (int j = 0; j < 16; j++) {
                    float2 rv = *(const float2*)(rp + j * 8);
                    float v0 = ac[j][2 * h] + bias2[j].x + rv.x;
                    float v1 = ac[j][2 * h + 1] + bias2[j].y + rv.y;
                    ac[j][2 * h] = v0;
                    ac[j][2 * h + 1] = v1;
                    sum += v0 + v1;
                }
                sum += __shfl_xor_sync(0xffffffffu, sum, 1);
                sum += __shfl_xor_sync(0xffffffffu, sum, 2);
                const float mean = sum * (1.f / 128.f);
                float var = 0.f;
#pragma unroll
                for (int j = 0; j < 16; j++) {
                    float v0 = ac[j][2 * h] - mean;
                    float v1 = ac[j][2 * h + 1] - mean;
                    ac[j][2 * h] = v0;
                    ac[j][2 * h + 1] = v1;
                    var += v0 * v0 + v1 * v1;
                }
                var += __shfl_xor_sync(0xffffffffu, var, 1);
                var += __shfl_xor_sync(0xffffffffu, var, 2);
                const float rs = rsqrtf(var * (1.f / 128.f) + 1e-5f);
                float* cp = C + (size_t)row * 128 + 2 * t4;
#pragma unroll
                for (int j = 0; j < 16; j++) {
                    float2 gv = *(const float2*)(gma + j * 8 + 2 * t4);
                    float2 tv = *(const float2*)(bta + j * 8 + 2 * t4);
                    float2 o;
                    o.x = fmaf(gv.x, ac[j][2 * h] * rs, tv.x);
                    o.y = fmaf(gv.y, ac[j][2 * h + 1] * rs, tv.y);
                    *(float2*)(cp + j * 8) = o;
                }
            }
        }
    } else {
#pragma unroll
        for (int i = 0; i < 2; i++) {
            float (*ac)[4] = i ? acc1 : acc0;
#pragma unroll
            for (int h = 0; h < 2; h++) {
                const int row = bm + wrow + i * 16 + h * 8 + g;
                float* cp = C + (size_t)row * ldc + bn + 2 * t4;
#pragma unroll
                for (int j = 0; j < 16; j++) {
                    float2 o;
                    o.x = ac[j][2 * h] + bias2[j].x;
                    o.y = ac[j][2 * h + 1] + bias2[j].y;
                    if (MODE == 1) { o.x = fmaxf(o.x, 0.f); o.y = fmaxf(o.y, 0.f); }
                    if (MODE == 3) { o.x = siluf(o.x); o.y = siluf(o.y); }
                    *(float2*)(cp + j * 8) = o;
                }
            }
        }
    }
}

// ---------------- time embedding ----------------
__global__ void __launch_bounds__(256) time_kernel(const int* __restrict__ ts,
                                                   const float* __restrict__ w1,
                                                   const float* __restrict__ b1,
                                                   const float* __restrict__ w2,
                                                   const float* __restrict__ b2) {
    __shared__ float te[128];
    __shared__ float hid[256];
    const int b = blockIdx.x, t = threadIdx.x;
    const float tf = (float)ts[b];
    if (t < 128) {
        int i = t & 63;
        float freq = expf(-0.14391156831212787f * (float)i);
        float arg = tf * freq;
        te[t] = (t < 64) ? cosf(arg) : sinf(arg);
    }
    __syncthreads();
    float a = b1[t];
    for (int i = 0; i < 128; i++) a = fmaf(te[i], w1[i * 256 + t], a);
    hid[t] = siluf(a);
    __syncthreads();
    if (t < 128) {
        float a2 = b2[t];
        for (int i = 0; i < 256; i++) a2 = fmaf(hid[i], w2[i * 128 + t], a2);
        g_comb[(size_t)b * 256 + t] = a2;
    }
}

// ---------------- cond layer1 ----------------
__global__ void __launch_bounds__(256) condh1_kernel(const float* __restrict__ cond,
                                                     const float* __restrict__ w1,
                                                     const float* __restrict__ b1) {
    const size_t row = (size_t)blockIdx.x * 32 + (threadIdx.x >> 3);
    const int dg = threadIdx.x & 7;
    const float* cp = cond + row * 6;
    float c0 = cp[0], c1 = cp[1], c2 = cp[2], c3 = cp[3], c4 = cp[4], c5 = cp[5];
    float o[8];
#pragma unroll
    for (int j = 0; j < 8; j++) {
        int dd = dg * 8 + j;
        float a = b1[dd];
        a = fmaf(c0, w1[0 * 64 + dd], a);
        a = fmaf(c1, w1[1 * 64 + dd], a);
        a = fmaf(c2, w1[2 * 64 + dd], a);
        a = fmaf(c3, w1[3 * 64 + dd], a);
        a = fmaf(c4, w1[4 * 64 + dd], a);
        a = fmaf(c5, w1[5 * 64 + dd], a);
        o[j] = siluf(a);
    }
    float4 v0, v1;
    v0.x = o[0]; v0.y = o[1]; v0.z = o[2]; v0.w = o[3];
    v1.x = o[4]; v1.y = o[5]; v1.z = o[6]; v1.w = o[7];
    *(float4*)(g_ch1 + row * 64 + dg * 8) = v0;
    *(float4*)(g_ch1 + row * 64 + dg * 8 + 4) = v1;
}

// ---------------- attention (fp32, f32x2) ----------------
#define ATTN_SMEM ((8192 + 128 * 129) * 4)
__global__ void __launch_bounds__(128) attn_kernel() {
    extern __shared__ float smem[];
    float (*ks)[32] = (float(*)[32])smem;
    float (*vs)[32] = (float(*)[32])(smem + 4096);
    float (*sc)[129] = (float(*)[129])(smem + 8192);
    const int b = blockIdx.x >> 2;
    const int hd = blockIdx.x & 3;
    const int t = threadIdx.x;
    const float* rowp = g_qkv + ((size_t)b * 128 + t) * 384;
#pragma unroll
    for (int c = 0; c < 8; c++)
        *(float4*)&ks[t][c * 4] = *(const float4*)(rowp + 128 + hd * 32 + c * 4);
#pragma unroll
    for (int c = 0; c < 8; c++)
        *(float4*)&vs[t][c * 4] = *(const float4*)(rowp + 256 + hd * 32 + c * 4);
    u64t q2[16];
#pragma unroll
    for (int c = 0; c < 8; c++) {
        ulonglong2 qv = *(const ulonglong2*)(rowp + hd * 32 + c * 4);
        q2[2 * c] = qv.x;
        q2[2 * c + 1] = qv.y;
    }
    __syncthreads();
    const float scale = 0.17677669529663687f;
    float m = -1e30f;
    for (int j = 0; j < 128; j++) {
        u64t d2 = 0ULL;
        const ulonglong2* kp = (const ulonglong2*)&ks[j][0];
#pragma unroll
        for (int c = 0; c < 8; c++) {
            ulonglong2 kv = kp[c];
            fma2(d2, q2[2 * c], kv.x);
            fma2(d2, q2[2 * c + 1], kv.y);
        }
        float2 dp = up2(d2);
        float s = (dp.x + dp.y) * scale;
        sc[t][j] = s;
        m = fmaxf(m, s);
    }
    float l = 0.f;
    u64t acc2[16];
#pragma unroll
    for (int i = 0; i < 16; i++) acc2[i] = 0ULL;
    for (int j = 0; j < 128; j++) {
        float e = __expf(sc[t][j] - m);
        l += e;
        u64t e2 = pk2(e, e);
        const ulonglong2* vp = (const ulonglong2*)&vs[j][0];
#pragma unroll
        for (int c = 0; c < 8; c++) {
            ulonglong2 vv = vp[c];
            fma2(acc2[2 * c], e2, vv.x);
            fma2(acc2[2 * c + 1], e2, vv.y);
        }
    }
    const float inv = 1.f / l;
    float* op = g_attn + ((size_t)b * 128 + t) * 128 + hd * 32;
#pragma unroll
    for (int c = 0; c < 16; c++) {
        float2 p = up2(acc2[c]);
        p.x *= inv;
        p.y *= inv;
        *(float2*)(op + 2 * c) = p;
    }
}

// ---------------- mean pool ----------------
__global__ void __launch_bounds__(128) pool_kernel() {
    const int b = blockIdx.x, d = threadIdx.x;
    const float* p = g_h + (size_t)b * 128 * 128 + d;
    float s = 0.f;
    for (int j = 0; j < 128; j++) s += p[j * 128];
    g_comb[(size_t)b * 256 + 128 + d] = s * (1.f / 128.f);
}

// ---------------- mixture weights ----------------
__global__ void __launch_bounds__(128) mw_kernel(const float* __restrict__ w1,
                                                 const float* __restrict__ b1,
                                                 const float* __restrict__ w2,
                                                 const float* __restrict__ b2) {
    __shared__ float scm[256];
    __shared__ float hid[128];
    __shared__ float lg[4];
    const int b = blockIdx.x, t = threadIdx.x;
    scm[t] = g_comb[(size_t)b * 256 + t];
    scm[128 + t] = g_comb[(size_t)b * 256 + 128 + t];
    __syncthreads();
    float a = b1[t];
    for (int i = 0; i < 256; i++) a = fmaf(scm[i], w1[i * 128 + t], a);
    hid[t] = siluf(a);
    __syncthreads();
    if (t < 4) {
        float a2 = b2[t];
        for (int j = 0; j < 128; j++) a2 = fmaf(hid[j], w2[j * 4 + t], a2);
        lg[t] = a2;
    }
    __syncthreads();
    if (t == 0) {
        float mm = fmaxf(fmaxf(lg[0], lg[1]), fmaxf(lg[2], lg[3]));
        float e0 = __expf(lg[0] - mm), e1 = __expf(lg[1] - mm);
        float e2 = __expf(lg[2] - mm), e3 = __expf(lg[3] - mm);
        float inv = 1.f / (e0 + e1 + e2 + e3);
        g_mw[(size_t)b * 4 + 0] = e0 * inv;
        g_mw[(size_t)b * 4 + 1] = e1 * inv;
        g_mw[(size_t)b * 4 + 2] = e2 * inv;
        g_mw[(size_t)b * 4 + 3] = e3 * inv;
    }
}

// ---------------- student fold pack (plain row-major [256,512]) ----------------
__global__ void __launch_bounds__(256) packsw1(const float* __restrict__ sw1) {
    int idx = blockIdx.x * 256 + threadIdx.x;  // < 256*512
    int i = idx >> 9;
    int n = idx & 511;
    g_sw1p[idx] = sw1[((size_t)(n >> 7) * 258 + 2 + i) * 128 + (n & 127)];
}

// ---------------- students ----------------
__global__ void __launch_bounds__(128) student_kernel(const float* __restrict__ x,
                                                      const float* __restrict__ sw1,
                                                      const float* __restrict__ sw2,
                                                      const float* __restrict__ sb2,
                                                      float* __restrict__ out) {
    __shared__ float sb[512], w0[512], w1s[512], s2a[512], s2b[512];
    __shared__ float smw[4], sbias2[8];
    const int b = blockIdx.x, t = threadIdx.x;
    for (int i = t; i < 512; i += 128) {
        sb[i] = g_base[(size_t)b * 512 + i];
        int k = i >> 7, j = i & 127;
        w0[i] = sw1[((size_t)k * 258 + 0) * 128 + j];
        w1s[i] = sw1[((size_t)k * 258 + 1) * 128 + j];
        s2a[i] = sw2[i * 2 + 0];
        s2b[i] = sw2[i * 2 + 1];
    }
    if (t < 4) smw[t] = g_mw[(size_t)b * 4 + t];
    if (t < 8) sbias2[t] = sb2[t];
    __syncthreads();
    const float x0 = x[(size_t)b * 256 + t];
    const float x1 = x[(size_t)b * 256 + 128 + t];
    float o0 = 0.f, o1 = 0.f;
#pragma unroll
    for (int k = 0; k < 4; k++) {
        float a0 = 0.f, a1 = 0.f;
        for (int j = 0; j < 128; j++) {
            int idx = k * 128 + j;
            float hv = tanh_fast(fmaf(x1, w1s[idx], fmaf(x0, w0[idx], sb[idx])));
            a0 = fmaf(hv, s2a[idx], a0);
            a1 = fmaf(hv, s2b[idx], a1);
        }
        float wk = smw[k];
        o0 = fmaf(wk, a0 + sbias2[k * 2 + 0], o0);
        o1 = fmaf(wk, a1 + sbias2[k * 2 + 1], o1);
    }
    out[(size_t)b * 256 + t] = o0;
    out[(size_t)b * 256 + 128 + t] = o1;
}

// ---------------- launcher ----------------
extern "C" void kernel_launch(void* const* d_in, const int* in_sizes, int n_in,
                              void* d_out, int out_size) {
    const float* x    = (const float*)d_in[0];
    const int*   ts   = (const int*)d_in[1];
    const float* cond = (const float*)d_in[2];
    const float* t_w1 = (const float*)d_in[3];
    const float* t_b1 = (const float*)d_in[4];
    const float* t_w2 = (const float*)d_in[5];
    const float* t_b2 = (const float*)d_in[6];
    const float* c_w1 = (const float*)d_in[7];
    const float* c_b1 = (const float*)d_in[8];
    const float* c_w2 = (const float*)d_in[9];
    const float* c_b2 = (const float*)d_in[10];
    const float* wqkv = (const float*)d_in[11];
    const float* bqkv = (const float*)d_in[12];
    const float* wo   = (const float*)d_in[13];
    const float* bo   = (const float*)d_in[14];
    const float* ln1g = (const float*)d_in[15];
    const float* ln1b = (const float*)d_in[16];
    const float* ffw1 = (const float*)d_in[17];
    const float* ffb1 = (const float*)d_in[18];
    const float* ffw2 = (const float*)d_in[19];
    const float* ffb2 = (const float*)d_in[20];
    const float* ln2g = (const float*)d_in[21];
    const float* ln2b = (const float*)d_in[22];
    const float* mww1 = (const float*)d_in[23];
    const float* mwb1 = (const float*)d_in[24];
    const float* mww2 = (const float*)d_in[25];
    const float* mwb2 = (const float*)d_in[26];
    const float* sw1  = (const float*)d_in[27];
    const float* sb1  = (const float*)d_in[28];
    const float* sw2  = (const float*)d_in[29];
    const float* sb2  = (const float*)d_in[30];
    float* out = (float*)d_out;

    float *gh, *gqkv, *gattn, *gch1, *gcomb, *gbase, *gsw1p;
    cudaGetSymbolAddress((void**)&gh, g_h);
    cudaGetSymbolAddress((void**)&gqkv, g_qkv);
    cudaGetSymbolAddress((void**)&gattn, g_attn);
    cudaGetSymbolAddress((void**)&gch1, g_ch1);
    cudaGetSymbolAddress((void**)&gcomb, g_comb);
    cudaGetSymbolAddress((void**)&gbase, g_base);
    cudaGetSymbolAddress((void**)&gsw1p, g_sw1p);

    cudaFuncSetAttribute(attn_kernel, cudaFuncAttributeMaxDynamicSharedMemorySize, ATTN_SMEM);
    cudaFuncSetAttribute(tgemm<0>, cudaFuncAttributeMaxDynamicSharedMemorySize, TG_SMEM);
    cudaFuncSetAttribute(tgemm<1>, cudaFuncAttributeMaxDynamicSharedMemorySize, TG_SMEM);
    cudaFuncSetAttribute(tgemm<2>, cudaFuncAttributeMaxDynamicSharedMemorySize, TG_SMEM);
    cudaFuncSetAttribute(tgemm<3>, cudaFuncAttributeMaxDynamicSharedMemorySize, TG_SMEM);

    time_kernel<<<B_, 256>>>(ts, t_w1, t_b1, t_w2, t_b2);
    condh1_kernel<<<MROWS / 32, 256>>>(cond, c_w1, c_b1);
    packsw1<<<(256 * 512) / 256, 256>>>(sw1);
    // cond layer2: silu(g_ch1 @ c_w2 + b)  [M,64]@[64,128]
    tgemm<3><<<dim3(1, MROWS / 128), 128, TG_SMEM>>>(gch1, 64, c_w2, 128, 64, c_b2,
                                                     nullptr, nullptr, nullptr, gh, 128);
    for (int l = 0; l < 2; l++) {
        // qkv
        tgemm<0><<<dim3(3, MROWS / 128), 128, TG_SMEM>>>(gh, 128, wqkv + (size_t)l * 49152, 384,
                                                         128, bqkv + l * 384, nullptr, nullptr,
                                                         nullptr, gqkv, 384);
        attn_kernel<<<B_ * 4, 128, ATTN_SMEM>>>();
        // o-proj + res + LN
        tgemm<2><<<dim3(1, MROWS / 128), 128, TG_SMEM>>>(gattn, 128, wo + (size_t)l * 16384, 128,
                                                         128, bo + l * 128, gh, ln1g + l * 128,
                                                         ln1b + l * 128, gh, 128);
        // ffn1 relu
        tgemm<1><<<dim3(2, MROWS / 128), 128, TG_SMEM>>>(gh, 128, ffw1 + (size_t)l * 32768, 256,
                                                         128, ffb1 + l * 256, nullptr, nullptr,
                                                         nullptr, gqkv, 256);
        // ffn2 + res + LN
        tgemm<2><<<dim3(1, MROWS / 128), 128, TG_SMEM>>>(gqkv, 256, ffw2 + (size_t)l * 32768, 128,
                                                         256, ffb2 + l * 128, gh, ln2g + l * 128,
                                                         ln2b + l * 128, gh, 128);
    }
    pool_kernel<<<B_, 128>>>();
    mw_kernel<<<B_, 128>>>(mww1, mwb1, mww2, mwb2);
    // student base: g_comb[4096,256] @ g_sw1p[256,512] + sb1
    tgemm<0><<<dim3(4, B_ / 128), 128, TG_SMEM>>>(gcomb, 256, gsw1p, 512, 256, sb1,
                                                  nullptr, nullptr, nullptr, gbase, 512);
    student_kernel<<<B_, 128>>>(x, sw1, sw2, sb2, out);
}